// round 5
// baseline (speedup 1.0000x reference)
#include <cuda_runtime.h>
#include <cstdint>

#define IN_COLS      8192
#define N_ROWS       8192
#define MAX_SLICES   1024
#define MAX_OUT_COLS 16384
#define ROWS_PER_BLK 32
#define GTHREADS     256

// out-col -> in-col map.
__device__ __align__(16) int g_col_idx[MAX_OUT_COLS];

// One block: decode slices (int32/int64 sniff), scan lengths, expand each
// slice directly (R2-style: cheaper than per-position binary search).
__global__ void __launch_bounds__(MAX_SLICES)
build_col_idx_kernel(const int* __restrict__ slices_raw, int n_slices) {
    __shared__ int s_scan[MAX_SLICES];
    __shared__ int s_is64;
    int t = threadIdx.x;

    if (t == 0) {
        // int64 LE: odd 32-bit words are zero high-halves; int32: odd words are ends >= 1.
        int z = 0;
        for (int k = 0; k < 4 && k < n_slices; k++)
            z |= slices_raw[4 * k + 1] | slices_raw[4 * k + 3];
        s_is64 = (z == 0) ? 1 : 0;
    }
    __syncthreads();
    int is64 = s_is64;

    int st = 0, len = 0;
    if (t < n_slices) {
        if (is64) { st = slices_raw[4 * t]; len = slices_raw[4 * t + 2] - st; }
        else      { st = slices_raw[2 * t]; len = slices_raw[2 * t + 1] - st; }
    }
    s_scan[t] = len;
    __syncthreads();

    // Hillis-Steele inclusive scan.
    #pragma unroll
    for (int d = 1; d < MAX_SLICES; d <<= 1) {
        int v = (t >= d) ? s_scan[t - d] : 0;
        __syncthreads();
        s_scan[t] += v;
        __syncthreads();
    }

    if (t < n_slices) {
        int off = s_scan[t] - len;   // exclusive prefix
        for (int j = 0; j < len; j++)
            g_col_idx[off + j] = st + j;
    }
}

// Scalar gather: one output column per thread (warp-contiguous index stream),
// 32 rows per thread for deep load MLP.
__global__ void __launch_bounds__(GTHREADS)
gather_kernel(const float* __restrict__ in, float* __restrict__ out, int out_cols) {
    int p = blockIdx.x * GTHREADS + threadIdx.x;
    if (p >= out_cols) return;

    int idx = g_col_idx[p];
    int r0  = blockIdx.y * ROWS_PER_BLK;

    const float* src = in  + (size_t)r0 * IN_COLS  + idx;
    float*       dst = out + (size_t)r0 * out_cols + p;

    #pragma unroll
    for (int j = 0; j < ROWS_PER_BLK; j++)
        dst[(size_t)j * out_cols] = __ldg(src + (size_t)j * IN_COLS);
}

extern "C" void kernel_launch(void* const* d_in, const int* in_sizes, int n_in,
                              void* d_out, int out_size) {
    const float* input      = (const float*)d_in[0];
    const int*   slices_raw = (const int*)d_in[1];
    float*       out        = (float*)d_out;

    int n_slices = in_sizes[1] / 2;      // 600
    int out_cols = out_size / N_ROWS;    // 12500

    build_col_idx_kernel<<<1, MAX_SLICES>>>(slices_raw, n_slices);

    dim3 grid((out_cols + GTHREADS - 1) / GTHREADS, N_ROWS / ROWS_PER_BLK);
    gather_kernel<<<grid, GTHREADS>>>(input, out, out_cols);
}